// round 14
// baseline (speedup 1.0000x reference)
#include <cuda_runtime.h>
#include <cuda_bf16.h>

#define N_NODES 16384
#define NCH 64
#define NSH 8                       // counter shards
#define SCAP 24                     // bucket capacity per (node, shard); mean 4
#define NODE_STRIDE (NSH * SCAP)    // 192 slots per node

// Scratch (allocation-free: device globals, zero-initialized at load)
__device__ __align__(16) __nv_bfloat162 g_seqTb[N_NODES * 32]; // node-major seq, bf16
__device__ __align__(16) float g_accT[N_NODES * NCH];          // gathered sums (fp32)
__device__ __align__(16) unsigned int g_deg2[NSH * N_NODES];   // sharded counters
__device__ __align__(16) int g_bucket[N_NODES * NODE_STRIDE];

// ---------------------------------------------------------------------------
// K1 (fused): blocks [0,256) transpose seq -> node-major bf16 (LDG.128 in,
// STG.128 out, 64x64 tiles); blocks [256,..) build sharded adjacency,
// 2 edges/thread (shard s = m&7).
// ---------------------------------------------------------------------------
__global__ void prep_build_kernel(const float* __restrict__ seq,
                                  const int* __restrict__ idx, int M) {
    int b = blockIdx.x;
    int tid = threadIdx.x;
    if (b < 256) {
        __shared__ float tile[64][65];     // [c][n_local]
        int nBase = b * 64;
        const float4* s4 = (const float4*)seq;   // row stride 4096 float4
        int f4 = tid & 15;                 // float4 column within 64 nodes
        int cq = tid >> 4;                 // 0..15
        #pragma unroll
        for (int p = 0; p < 4; p++) {
            int c = p * 16 + cq;
            float4 v = s4[c * 4096 + (nBase >> 2) + f4];
            tile[c][f4 * 4 + 0] = v.x;
            tile[c][f4 * 4 + 1] = v.y;
            tile[c][f4 * 4 + 2] = v.z;
            tile[c][f4 * 4 + 3] = v.w;
        }
        __syncthreads();
        uint4* dst = (uint4*)g_seqTb;      // node row = 8 uint4
        #pragma unroll
        for (int r = 0; r < 2; r++) {
            int i = tid + r * 256;
            int nl = i >> 3;
            int q = i & 7;                 // channels q*8 .. q*8+7
            int c0 = q * 8;
            __nv_bfloat162 b0 = __floats2bfloat162_rn(tile[c0 + 0][nl], tile[c0 + 1][nl]);
            __nv_bfloat162 b1 = __floats2bfloat162_rn(tile[c0 + 2][nl], tile[c0 + 3][nl]);
            __nv_bfloat162 b2 = __floats2bfloat162_rn(tile[c0 + 4][nl], tile[c0 + 5][nl]);
            __nv_bfloat162 b3 = __floats2bfloat162_rn(tile[c0 + 6][nl], tile[c0 + 7][nl]);
            uint4 u;
            u.x = *reinterpret_cast<unsigned int*>(&b0);
            u.y = *reinterpret_cast<unsigned int*>(&b1);
            u.z = *reinterpret_cast<unsigned int*>(&b2);
            u.w = *reinterpret_cast<unsigned int*>(&b3);
            dst[(nBase + nl) * 8 + q] = u;
        }
    } else {
        int hb = b - 256;
        int m0 = (hb * 256 + tid) * 2;     // multiple of 2 -> shard pair
        int sb = (m0 & 7);                 // 0,2,4,6
        if (m0 + 1 < M) {
            int4 v0 = ((const int4*)idx)[m0 >> 1];
            int r0 = (int)atomicAdd(&g_deg2[(sb + 0) * N_NODES + v0.x], 1u);
            int r1 = (int)atomicAdd(&g_deg2[(sb + 1) * N_NODES + v0.z], 1u);
            if (r0 < SCAP) g_bucket[v0.x * NODE_STRIDE + (sb + 0) * SCAP + r0] = v0.y;
            if (r1 < SCAP) g_bucket[v0.z * NODE_STRIDE + (sb + 1) * SCAP + r1] = v0.w;
        } else if (m0 < M) {
            int a = idx[2 * m0], bb = idx[2 * m0 + 1];
            int s = m0 & 7;
            int r = (int)atomicAdd(&g_deg2[s * N_NODES + a], 1u);
            if (r < SCAP) g_bucket[a * NODE_STRIDE + s * SCAP + r] = bb;
        }
    }
}

// ---------------------------------------------------------------------------
// K2: gather, TWO nodes per warp (prologue amortized). Lanes 0-7 hold node0's
// shard counts, 8-15 node1's (one LDG, one segmented 3-shfl scan). Gather:
// quads 0-1 process node0 edges, quads 2-3 node1; per macro-batch one bucket
// LDG covers 16 ranks of EACH node; inner loop streams 4 rows/iteration.
// bf16 -> fp32 exact via shift; fp32 accumulate; .cs streaming stores.
// ---------------------------------------------------------------------------
__global__ void __launch_bounds__(256) gather_kernel() {
    const unsigned FULL = 0xffffffffu;
    int w = threadIdx.x >> 5;
    int lane = threadIdx.x & 31;
    int quad = lane >> 3;              // 0..3
    int l8 = lane & 7;                 // uint4 slot within row
    int n0 = (blockIdx.x << 4) + (w << 1);   // warp handles n0, n0+1

    // lanes 0-7: shards of n0; lanes 8-15: shards of n1
    int craw = 0;
    if (lane < 16)
        craw = (int)__ldg(&g_deg2[(lane & 7) * N_NODES + n0 + (lane >> 3)]);
    int c = craw < SCAP ? craw : SCAP;
    // segmented inclusive scan within 8-lane groups
    int pre = c;
    #pragma unroll
    for (int off = 1; off < 8; off <<= 1) {
        int y = __shfl_up_sync(FULL, pre, off);
        if ((lane & 7) >= off) pre += y;
    }
    // bounds for MY gather node (lanes 0-15 -> node0, 16-31 -> node1)
    int sb = (lane >> 4) << 3;         // 0 or 8: source group base
    int P0 = __shfl_sync(FULL, pre, sb + 0);
    int P1 = __shfl_sync(FULL, pre, sb + 1);
    int P2 = __shfl_sync(FULL, pre, sb + 2);
    int P3 = __shfl_sync(FULL, pre, sb + 3);
    int P4 = __shfl_sync(FULL, pre, sb + 4);
    int P5 = __shfl_sync(FULL, pre, sb + 5);
    int P6 = __shfl_sync(FULL, pre, sb + 6);
    int total = __shfl_sync(FULL, pre, sb + 7);   // my node's (clamped) edge count
    int totBoth = max(total, __shfl_xor_sync(FULL, total, 16));

    const uint4* sp = (const uint4*)g_seqTb;   // row = 8 uint4 (64 ch)
    float acc[8];
    #pragma unroll
    for (int k = 0; k < 8; k++) acc[k] = 0.0f;
    int base = (n0 + (lane >> 4)) * NODE_STRIDE;

    int nBatch = (totBoth + 15) >> 4;
    for (int t = 0; t < nBatch; t++) {
        int r = (t << 4) + (lane & 15);          // rank within MY node
        int sSel = 0, excl = 0;
        if (r >= P0) { sSel = 1; excl = P0; }
        if (r >= P1) { sSel = 2; excl = P1; }
        if (r >= P2) { sSel = 3; excl = P2; }
        if (r >= P3) { sSel = 4; excl = P3; }
        if (r >= P4) { sSel = 5; excl = P4; }
        if (r >= P5) { sSel = 6; excl = P5; }
        if (r >= P6) { sSel = 7; excl = P6; }
        int b = 0;
        if (r < total) b = __ldg(&g_bucket[base + sSel * SCAP + (r - excl)]);

        // inner: iteration it, quad q processes rank 16t + 2it + (q&1) of
        // node (q>>1); that rank lives in lane 2it + (q&1) + ((q>>1)<<4).
        #pragma unroll
        for (int it = 0; it < 8; it++) {
            int src = 2 * it + (quad & 1) + ((quad >> 1) << 4);
            int s = __shfl_sync(FULL, b, src);
            int er = (t << 4) + 2 * it + (quad & 1);
            if (er < total) {                    // my quad's node == my node
                uint4 u = sp[s * 8 + l8];
                acc[0] += __uint_as_float(u.x << 16);
                acc[1] += __uint_as_float(u.x & 0xFFFF0000u);
                acc[2] += __uint_as_float(u.y << 16);
                acc[3] += __uint_as_float(u.y & 0xFFFF0000u);
                acc[4] += __uint_as_float(u.z << 16);
                acc[5] += __uint_as_float(u.z & 0xFFFF0000u);
                acc[6] += __uint_as_float(u.w << 16);
                acc[7] += __uint_as_float(u.w & 0xFFFF0000u);
            }
        }
    }
    // combine quad pairs: (0,1) -> node0, (2,3) -> node1
    #pragma unroll
    for (int k = 0; k < 8; k++)
        acc[k] += __shfl_xor_sync(FULL, acc[k], 8);
    if ((quad & 1) == 0) {
        int nstore = n0 + (quad >> 1);
        float* dst = g_accT + nstore * NCH + l8 * 8;
        asm volatile("st.global.cs.v4.f32 [%0], {%1,%2,%3,%4};"
                     :: "l"(dst), "f"(acc[0]), "f"(acc[1]), "f"(acc[2]), "f"(acc[3])
                     : "memory");
        asm volatile("st.global.cs.v4.f32 [%0], {%1,%2,%3,%4};"
                     :: "l"(dst + 4), "f"(acc[4]), "f"(acc[5]), "f"(acc[6]), "f"(acc[7])
                     : "memory");
    }
}

// ---------------------------------------------------------------------------
// K3: combine. out[o,n] = deg[n]*dot(W0[o,:],seq[:,n]) + dot(W1[o,:],accT[n,:])
// Degree computed HERE by summing the 8 shard counters (then zeroing them for
// replay safety). 512 threads, 64 nodes/block, grid 256.
// ---------------------------------------------------------------------------
__global__ void out_kernel(const float* __restrict__ seq,
                           const float* __restrict__ W, float* __restrict__ out) {
    extern __shared__ float smem[];
    float* Ws0 = smem;                    // [c][64] scalar
    float* Ws1 = Ws0 + 4096;
    float* hs = Ws1 + 4096;               // [64][65] fp32 seq
    float* gs = hs + 64 * 65;             // [64][65] gathered sums
    float* degs = gs + 64 * 65;           // [64]

    int tid = threadIdx.x;
    int nodeBase = blockIdx.x * 64;

    const float2* W2 = (const float2*)W;  // W[o][c][k] -> float2 at o*64+c
    #pragma unroll
    for (int i = tid; i < 4096; i += 512) {
        int o = i >> 6, c = i & 63;
        float2 wv = W2[i];
        Ws0[c * 64 + o] = wv.x;
        Ws1[c * 64 + o] = wv.y;
    }
    if (tid < 64) {
        int nn = nodeBase + tid;
        unsigned d = 0;
        #pragma unroll
        for (int s = 0; s < NSH; s++) {
            d += g_deg2[s * N_NODES + nn];
            g_deg2[s * N_NODES + nn] = 0u;   // reset for next replay
        }
        degs[tid] = (float)d;
    }
    for (int i = tid; i < 4096; i += 512) {
        int c = i >> 6, j = i & 63;       // coalesced: j fast over c-major seq
        hs[c * 65 + j] = seq[c * N_NODES + nodeBase + j];
    }
    for (int i = tid; i < 4096; i += 512) {
        int j = i >> 6, c = i & 63;       // coalesced: c fast over node-major accT
        gs[c * 65 + j] = g_accT[(nodeBase + j) * NCH + c];
    }
    __syncthreads();

    int j = tid & 63;
    int og = tid >> 6;                    // outputs o = og*8 .. og*8+7
    float4 h0 = make_float4(0.f, 0.f, 0.f, 0.f), h1 = h0;
    float4 g0 = h0, g1 = h0;
    #pragma unroll
    for (int c = 0; c < 64; c++) {
        float h = hs[c * 65 + j];
        float gg = gs[c * 65 + j];
        float4 w00 = *(const float4*)&Ws0[c * 64 + og * 8 + 0];
        float4 w01 = *(const float4*)&Ws0[c * 64 + og * 8 + 4];
        float4 w10 = *(const float4*)&Ws1[c * 64 + og * 8 + 0];
        float4 w11 = *(const float4*)&Ws1[c * 64 + og * 8 + 4];
        h0.x += w00.x * h; h0.y += w00.y * h; h0.z += w00.z * h; h0.w += w00.w * h;
        h1.x += w01.x * h; h1.y += w01.y * h; h1.z += w01.z * h; h1.w += w01.w * h;
        g0.x += w10.x * gg; g0.y += w10.y * gg; g0.z += w10.z * gg; g0.w += w10.w * gg;
        g1.x += w11.x * gg; g1.y += w11.y * gg; g1.z += w11.z * gg; g1.w += w11.w * gg;
    }
    float d = degs[j];
    int o = og * 8;
    int n = nodeBase + j;
    out[(o + 0) * N_NODES + n] = d * h0.x + g0.x;
    out[(o + 1) * N_NODES + n] = d * h0.y + g0.y;
    out[(o + 2) * N_NODES + n] = d * h0.z + g0.z;
    out[(o + 3) * N_NODES + n] = d * h0.w + g0.w;
    out[(o + 4) * N_NODES + n] = d * h1.x + g1.x;
    out[(o + 5) * N_NODES + n] = d * h1.y + g1.y;
    out[(o + 6) * N_NODES + n] = d * h1.z + g1.z;
    out[(o + 7) * N_NODES + n] = d * h1.w + g1.w;
}

// ---------------------------------------------------------------------------
extern "C" void kernel_launch(void* const* d_in, const int* in_sizes, int n_in,
                              void* d_out, int out_size) {
    const float* seq = (const float*)d_in[0];   // (1,64,16384) f32
    const int*   idx = (const int*)d_in[1];     // (2M,) int32
    const float* W   = (const float*)d_in[2];   // (64,64,2) f32
    float*       out = (float*)d_out;           // (1,64,16384) f32

    int twoM = in_sizes[1];
    int M = twoM / 2;
    int eb = (M + 511) / 512;                   // 2 edges/thread, 256 threads

    const int SMEM = (4096 * 2 + 64 * 65 * 2 + 64) * 4;   // 66304 B
    cudaFuncSetAttribute(out_kernel,
                         cudaFuncAttributeMaxDynamicSharedMemorySize, SMEM);

    prep_build_kernel<<<256 + eb, 256>>>(seq, idx, M);
    gather_kernel<<<N_NODES / 16, 256>>>();
    out_kernel<<<N_NODES / 64, 512, SMEM>>>(seq, W, out);
}

// round 15
// speedup vs baseline: 1.0449x; 1.0449x over previous
#include <cuda_runtime.h>
#include <cuda_bf16.h>

#define N_NODES 16384
#define NCH 64
#define NSH 8                       // counter shards
#define SCAP 24                     // bucket capacity per (node, shard); mean 4
#define NODE_STRIDE (NSH * SCAP)    // 192 slots per node

// Scratch (allocation-free: device globals, zero-initialized at load)
__device__ __align__(16) __nv_bfloat162 g_seqTb[N_NODES * 32]; // node-major seq, bf16
__device__ __align__(16) float g_accT[N_NODES * NCH];          // gathered sums (fp32)
__device__ __align__(16) unsigned int g_deg2[NSH * N_NODES];   // sharded counters
__device__ __align__(16) int g_degn[N_NODES];                  // true degree
__device__ __align__(16) int g_bucket[N_NODES * NODE_STRIDE];

// ---------------------------------------------------------------------------
// K1 (fused): blocks [0,256) transpose seq -> node-major bf16 (LDG.128 in,
// STG.128 out, 64x64 tiles); blocks [256,..) build sharded adjacency,
// 2 edges/thread (shard s = m&7). Triggers PDL completion per block.
// ---------------------------------------------------------------------------
__global__ void prep_build_kernel(const float* __restrict__ seq,
                                  const int* __restrict__ idx, int M) {
    int b = blockIdx.x;
    int tid = threadIdx.x;
    if (b < 256) {
        __shared__ float tile[64][65];     // [c][n_local]
        int nBase = b * 64;
        const float4* s4 = (const float4*)seq;   // row stride 4096 float4
        int f4 = tid & 15;                 // float4 column within 64 nodes
        int cq = tid >> 4;                 // 0..15
        #pragma unroll
        for (int p = 0; p < 4; p++) {
            int c = p * 16 + cq;
            float4 v = s4[c * 4096 + (nBase >> 2) + f4];
            tile[c][f4 * 4 + 0] = v.x;
            tile[c][f4 * 4 + 1] = v.y;
            tile[c][f4 * 4 + 2] = v.z;
            tile[c][f4 * 4 + 3] = v.w;
        }
        __syncthreads();
        uint4* dst = (uint4*)g_seqTb;      // node row = 8 uint4
        #pragma unroll
        for (int r = 0; r < 2; r++) {
            int i = tid + r * 256;
            int nl = i >> 3;
            int q = i & 7;                 // channels q*8 .. q*8+7
            int c0 = q * 8;
            __nv_bfloat162 b0 = __floats2bfloat162_rn(tile[c0 + 0][nl], tile[c0 + 1][nl]);
            __nv_bfloat162 b1 = __floats2bfloat162_rn(tile[c0 + 2][nl], tile[c0 + 3][nl]);
            __nv_bfloat162 b2 = __floats2bfloat162_rn(tile[c0 + 4][nl], tile[c0 + 5][nl]);
            __nv_bfloat162 b3 = __floats2bfloat162_rn(tile[c0 + 6][nl], tile[c0 + 7][nl]);
            uint4 u;
            u.x = *reinterpret_cast<unsigned int*>(&b0);
            u.y = *reinterpret_cast<unsigned int*>(&b1);
            u.z = *reinterpret_cast<unsigned int*>(&b2);
            u.w = *reinterpret_cast<unsigned int*>(&b3);
            dst[(nBase + nl) * 8 + q] = u;
        }
    } else {
        int hb = b - 256;
        int m0 = (hb * 256 + tid) * 2;     // multiple of 2 -> shard pair
        int sb = (m0 & 7);                 // 0,2,4,6
        if (m0 + 1 < M) {
            int4 v0 = ((const int4*)idx)[m0 >> 1];
            int r0 = (int)atomicAdd(&g_deg2[(sb + 0) * N_NODES + v0.x], 1u);
            int r1 = (int)atomicAdd(&g_deg2[(sb + 1) * N_NODES + v0.z], 1u);
            if (r0 < SCAP) g_bucket[v0.x * NODE_STRIDE + (sb + 0) * SCAP + r0] = v0.y;
            if (r1 < SCAP) g_bucket[v0.z * NODE_STRIDE + (sb + 1) * SCAP + r1] = v0.w;
        } else if (m0 < M) {
            int a = idx[2 * m0], bb = idx[2 * m0 + 1];
            int s = m0 & 7;
            int r = (int)atomicAdd(&g_deg2[s * N_NODES + a], 1u);
            if (r < SCAP) g_bucket[a * NODE_STRIDE + s * SCAP + r] = bb;
        }
    }
    cudaTriggerProgrammaticLaunchCompletion();
}

// ---------------------------------------------------------------------------
// K2: gather over ragged sharded buckets, bf16 rows (ROUND-9 core). One warp
// per node. Quarter-warp per edge: lane (quad, l8) loads uint4 = 8 bf16
// channels; 4 edges concurrent. bf16 -> fp32 exact via shift; fp32 accumulate.
// PDL: grid-sync at entry (everything depends on prep); triggers at end.
// ---------------------------------------------------------------------------
__global__ void __launch_bounds__(256) gather_kernel() {
    const unsigned FULL = 0xffffffffu;
    int n = (blockIdx.x << 3) + (threadIdx.x >> 5);
    int lane = threadIdx.x & 31;
    int quad = lane >> 3;
    int l8 = lane & 7;

    cudaGridDependencySynchronize();   // wait for prep (deg2/bucket/seqTb)

    int craw = (lane < 8) ? (int)__ldg(&g_deg2[lane * N_NODES + n]) : 0;
    int c = craw < SCAP ? craw : SCAP;
    int pre = c;
    #pragma unroll
    for (int off = 1; off < 8; off <<= 1) {
        int y = __shfl_up_sync(FULL, pre, off);
        if (lane >= off) pre += y;
    }
    int P0 = __shfl_sync(FULL, pre, 0);
    int P1 = __shfl_sync(FULL, pre, 1);
    int P2 = __shfl_sync(FULL, pre, 2);
    int P3 = __shfl_sync(FULL, pre, 3);
    int P4 = __shfl_sync(FULL, pre, 4);
    int P5 = __shfl_sync(FULL, pre, 5);
    int P6 = __shfl_sync(FULL, pre, 6);
    int total = __shfl_sync(FULL, pre, 7);

    int degRaw = craw;
    #pragma unroll
    for (int off = 16; off >= 1; off >>= 1)
        degRaw += __shfl_xor_sync(FULL, degRaw, off);
    if (lane == 0) g_degn[n] = degRaw;

    const uint4* sp = (const uint4*)g_seqTb;   // row = 8 uint4 (64 ch)
    float acc[8];
    #pragma unroll
    for (int k = 0; k < 8; k++) acc[k] = 0.0f;
    int base = n * NODE_STRIDE;

    for (int e = 0; e < total; e += 32) {
        int nb = total - e;
        if (nb > 32) nb = 32;
        int r = e + lane;
        int sSel = 0, excl = 0;
        if (r >= P0) { sSel = 1; excl = P0; }
        if (r >= P1) { sSel = 2; excl = P1; }
        if (r >= P2) { sSel = 3; excl = P2; }
        if (r >= P3) { sSel = 4; excl = P3; }
        if (r >= P4) { sSel = 5; excl = P4; }
        if (r >= P5) { sSel = 6; excl = P5; }
        if (r >= P6) { sSel = 7; excl = P6; }
        int b = (lane < nb) ? __ldg(&g_bucket[base + sSel * SCAP + (r - excl)]) : 0;

        if (nb == 32) {
            #pragma unroll
            for (int it = 0; it < 8; it++) {
                int s = __shfl_sync(FULL, b, 4 * it + quad);
                uint4 u = sp[s * 8 + l8];
                acc[0] += __uint_as_float(u.x << 16);
                acc[1] += __uint_as_float(u.x & 0xFFFF0000u);
                acc[2] += __uint_as_float(u.y << 16);
                acc[3] += __uint_as_float(u.y & 0xFFFF0000u);
                acc[4] += __uint_as_float(u.z << 16);
                acc[5] += __uint_as_float(u.z & 0xFFFF0000u);
                acc[6] += __uint_as_float(u.w << 16);
                acc[7] += __uint_as_float(u.w & 0xFFFF0000u);
            }
        } else {
            int nq = (nb + 3) >> 2;
            for (int it = 0; it < nq; it++) {
                int eidx = 4 * it + quad;
                int src = eidx < nb ? eidx : 0;
                int s = __shfl_sync(FULL, b, src);
                if (eidx < nb) {
                    uint4 u = sp[s * 8 + l8];
                    acc[0] += __uint_as_float(u.x << 16);
                    acc[1] += __uint_as_float(u.x & 0xFFFF0000u);
                    acc[2] += __uint_as_float(u.y << 16);
                    acc[3] += __uint_as_float(u.y & 0xFFFF0000u);
                    acc[4] += __uint_as_float(u.z << 16);
                    acc[5] += __uint_as_float(u.z & 0xFFFF0000u);
                    acc[6] += __uint_as_float(u.w << 16);
                    acc[7] += __uint_as_float(u.w & 0xFFFF0000u);
                }
            }
        }
    }
    #pragma unroll
    for (int k = 0; k < 8; k++) {
        acc[k] += __shfl_xor_sync(FULL, acc[k], 8);
        acc[k] += __shfl_xor_sync(FULL, acc[k], 16);
    }
    if (quad == 0) {
        float4* dst = (float4*)g_accT + n * 16 + l8 * 2;
        dst[0] = make_float4(acc[0], acc[1], acc[2], acc[3]);
        dst[1] = make_float4(acc[4], acc[5], acc[6], acc[7]);
    }
    cudaTriggerProgrammaticLaunchCompletion();
}

// ---------------------------------------------------------------------------
// K3: combine (ROUND-9 core). PDL: stage W and hs (inputs only) BEFORE the
// grid-sync, then consume gather's degn/accT. Zeroes g_deg2 (replay safety;
// safe: gather fully complete at sync). 512 threads, 64 nodes/block, grid 256.
// ---------------------------------------------------------------------------
__global__ void out_kernel(const float* __restrict__ seq,
                           const float* __restrict__ W, float* __restrict__ out) {
    extern __shared__ float smem[];
    float* Ws0 = smem;                    // [c][64] scalar
    float* Ws1 = Ws0 + 4096;
    float* hs = Ws1 + 4096;               // [64][65] fp32 seq
    float* gs = hs + 64 * 65;             // [64][65] gathered sums
    float* degs = gs + 64 * 65;           // [64]

    int tid = threadIdx.x;
    int nodeBase = blockIdx.x * 64;

    // --- pre-sync: depends only on kernel inputs (W, seq) ---
    const float2* W2 = (const float2*)W;  // W[o][c][k] -> float2 at o*64+c
    #pragma unroll
    for (int i = tid; i < 4096; i += 512) {
        int o = i >> 6, c = i & 63;
        float2 wv = W2[i];
        Ws0[c * 64 + o] = wv.x;
        Ws1[c * 64 + o] = wv.y;
    }
    for (int i = tid; i < 4096; i += 512) {
        int c = i >> 6, j = i & 63;       // coalesced: j fast over c-major seq
        hs[c * 65 + j] = seq[c * N_NODES + nodeBase + j];
    }

    cudaGridDependencySynchronize();      // wait for gather (degn, accT)

    if (tid < 64) degs[tid] = (float)g_degn[nodeBase + tid];
    {   // zero sharded counters for next replay (8 shards x 64 nodes)
        int s = tid >> 6, nn = nodeBase + (tid & 63);
        g_deg2[s * N_NODES + nn] = 0u;
    }
    for (int i = tid; i < 4096; i += 512) {
        int j = i >> 6, c = i & 63;       // coalesced: c fast over node-major accT
        gs[c * 65 + j] = g_accT[(nodeBase + j) * NCH + c];
    }
    __syncthreads();

    int j = tid & 63;
    int og = tid >> 6;                    // outputs o = og*8 .. og*8+7
    float4 h0 = make_float4(0.f, 0.f, 0.f, 0.f), h1 = h0;
    float4 g0 = h0, g1 = h0;
    #pragma unroll
    for (int c = 0; c < 64; c++) {
        float h = hs[c * 65 + j];
        float gg = gs[c * 65 + j];
        float4 w00 = *(const float4*)&Ws0[c * 64 + og * 8 + 0];
        float4 w01 = *(const float4*)&Ws0[c * 64 + og * 8 + 4];
        float4 w10 = *(const float4*)&Ws1[c * 64 + og * 8 + 0];
        float4 w11 = *(const float4*)&Ws1[c * 64 + og * 8 + 4];
        h0.x += w00.x * h; h0.y += w00.y * h; h0.z += w00.z * h; h0.w += w00.w * h;
        h1.x += w01.x * h; h1.y += w01.y * h; h1.z += w01.z * h; h1.w += w01.w * h;
        g0.x += w10.x * gg; g0.y += w10.y * gg; g0.z += w10.z * gg; g0.w += w10.w * gg;
        g1.x += w11.x * gg; g1.y += w11.y * gg; g1.z += w11.z * gg; g1.w += w11.w * gg;
    }
    float d = degs[j];
    int o = og * 8;
    int n = nodeBase + j;
    out[(o + 0) * N_NODES + n] = d * h0.x + g0.x;
    out[(o + 1) * N_NODES + n] = d * h0.y + g0.y;
    out[(o + 2) * N_NODES + n] = d * h0.z + g0.z;
    out[(o + 3) * N_NODES + n] = d * h0.w + g0.w;
    out[(o + 4) * N_NODES + n] = d * h1.x + g1.x;
    out[(o + 5) * N_NODES + n] = d * h1.y + g1.y;
    out[(o + 6) * N_NODES + n] = d * h1.z + g1.z;
    out[(o + 7) * N_NODES + n] = d * h1.w + g1.w;
}

// ---------------------------------------------------------------------------
extern "C" void kernel_launch(void* const* d_in, const int* in_sizes, int n_in,
                              void* d_out, int out_size) {
    const float* seq = (const float*)d_in[0];   // (1,64,16384) f32
    const int*   idx = (const int*)d_in[1];     // (2M,) int32
    const float* W   = (const float*)d_in[2];   // (64,64,2) f32
    float*       out = (float*)d_out;           // (1,64,16384) f32

    int twoM = in_sizes[1];
    int M = twoM / 2;
    int eb = (M + 511) / 512;                   // 2 edges/thread, 256 threads

    const int SMEM = (4096 * 2 + 64 * 65 * 2 + 64) * 4;   // 66304 B
    cudaFuncSetAttribute(out_kernel,
                         cudaFuncAttributeMaxDynamicSharedMemorySize, SMEM);

    prep_build_kernel<<<256 + eb, 256>>>(seq, idx, M);

    cudaLaunchAttribute pdl[1];
    pdl[0].id = cudaLaunchAttributeProgrammaticStreamSerialization;
    pdl[0].val.programmaticStreamSerializationAllowed = 1;

    {   // gather with PDL edge from prep
        cudaLaunchConfig_t cfg = {};
        cfg.gridDim = dim3(N_NODES / 8);
        cfg.blockDim = dim3(256);
        cfg.dynamicSmemBytes = 0;
        cfg.stream = 0;
        cfg.attrs = pdl;
        cfg.numAttrs = 1;
        cudaLaunchKernelEx(&cfg, gather_kernel);
    }
    {   // out with PDL edge from gather
        cudaLaunchConfig_t cfg = {};
        cfg.gridDim = dim3(N_NODES / 64);
        cfg.blockDim = dim3(512);
        cfg.dynamicSmemBytes = SMEM;
        cfg.stream = 0;
        cfg.attrs = pdl;
        cfg.numAttrs = 1;
        cudaLaunchKernelEx(&cfg, out_kernel, seq, W, out);
    }
}